// round 17
// baseline (speedup 1.0000x reference)
#include <cuda_runtime.h>
#include <cstdint>

// Problem constants (fixed by the reference)
#define NQ       64            // qubits
#define NS       4096          // samples per unique circuit
#define NU       256           // unique circuits
#define NB       1024          // batch size
#define PARTS    8             // blocks per circuit
#define NSB      (NS / PARTS)  // samples per block = 512
#define CHUNKS_B (NSB / 32)    // 16 chunks of 32 samples
#define THREADS  256
#define NWARPS   (THREADS / 32)
#define GRID     (NU * PARTS)  // 2048
#define WAVE     740           // validated prefetch distance
#define SW       72            // S row stride in words (64 qubits + ones + pad)
#define NSLOT    128           // 512 samples / 4 per word

// Per-(circuit,part) partial energy sums and completion counter.
__device__ float        g_part[GRID];
__device__ unsigned int g_count;   // zero-initialized; reset by last block

__device__ __forceinline__ void mma_s8(int* c, uint32_t a0, uint32_t a1,
                                       uint32_t a2, uint32_t a3,
                                       uint32_t b0, uint32_t b1)
{
    asm volatile(
        "mma.sync.aligned.m16n8k32.row.col.s32.s8.s8.s32 "
        "{%0,%1,%2,%3}, {%4,%5,%6,%7}, {%8,%9}, {%0,%1,%2,%3};"
        : "+r"(c[0]), "+r"(c[1]), "+r"(c[2]), "+r"(c[3])
        : "r"(a0), "r"(a1), "r"(a2), "r"(a3), "r"(b0), "r"(b1));
}

// One block per (circuit, eighth).
//   Phase 1: coalesced streaming LDG.128 (MLP=8) -> byte-pack (PRMT) ->
//            smem S[slot][qubit] of int8 spins (+1/-1), plus an all-ones
//            row (qubit 64) that makes the bias term a free GEMM column.
//   Prefetch: entire 128 KB slab of block (bx+WAVE) into L2 (validated).
//   Phase 2: C[64][65] = S^T S via warp-level IMMA m16n8k32; fold with K
//            (full matrix, diagonal included) and bias from the ones column.
__global__ void __launch_bounds__(THREADS)
energy_kernel(const int* __restrict__ samples,
              const int* __restrict__ idx,
              const float* __restrict__ bias,
              const float* __restrict__ kern,
              float* __restrict__ out)
{
    __shared__ uint32_t S[NSLOT * SW];   // 36 KB spin matrix (s8), padded
    __shared__ float red[NWARPS];
    __shared__ bool s_last;

    const int tid  = threadIdx.x;
    const int lane = tid & 31;
    const int w    = tid >> 5;
    const int bx   = blockIdx.x;

    // Ones row (qubit 64) + zero the pad columns 65..71.
    if (tid < NSLOT) S[tid * SW + 64] = 0x01010101u;
    for (int x = tid; x < NSLOT * 7; x += THREADS)
        S[(x / 7) * SW + 65 + (x % 7)] = 0u;

    // Block bx's data: contiguous 128 KB slabs (8192 uint4).
    const uint4* base = (const uint4*)samples + (size_t)bx * 8192;

    // Thread (i, h): i = lane&15 -> qubit group 4i..4i+3; h = lane>>4 ->
    // sample parity. After shfl_xor(16), thread holds both parities and
    // writes qubits 4i+2h, 4i+2h+1 for its slots.
    const int i = lane & 15;
    const int h = lane >> 4;
    const uint32_t sel = (uint32_t)(2 * h) | ((uint32_t)(2 * h + 4) << 4);
    const uint32_t sel1 = sel + 0x11u;     // qubit offset 2h+1

    // ---------------- Phase 1: load -> pack -> transpose to S --------------
    #pragma unroll
    for (int k = 0; k < 2; k++) {                 // 2 chunks per warp
        const int ch = w * 2 + k;
        const uint4* P = base + (size_t)ch * 512; // 32 rows * 16 uint4

        #pragma unroll
        for (int half = 0; half < 2; half++) {
            uint4 v[8];
            #pragma unroll
            for (int jj = 0; jj < 8; jj++)        // coalesced, MLP=8
                v[jj] = __ldcs(&P[(half * 8 + jj) * 32 + lane]);

            // Pack each uint4 (4 qubit values of one sample) into 4 bytes.
            uint32_t B[8];
            #pragma unroll
            for (int jj = 0; jj < 8; jj++) {
                uint32_t t1 = __byte_perm(v[jj].x, v[jj].y, 0x0040);
                uint32_t t2 = __byte_perm(v[jj].z, v[jj].w, 0x0040);
                B[jj] = __byte_perm(t1, t2, 0x5410);
            }

            // Exchange parities and emit S words (4 samples x 1 qubit).
            #pragma unroll
            for (int gg = 0; gg < 2; gg++) {      // g = half*2+gg
                const int g = half * 2 + gg;
                uint32_t X[4], Y[4];
                #pragma unroll
                for (int jj = 0; jj < 4; jj++) {
                    const uint32_t own  = B[gg * 4 + jj];
                    const uint32_t recv = __shfl_xor_sync(0xffffffffu, own, 16);
                    X[jj] = h ? recv : own;       // h=0 data
                    Y[jj] = h ? own  : recv;      // h=1 data
                }
                const int q0 = 4 * i + 2 * h;
                #pragma unroll
                for (int d = 0; d < 2; d++) {     // slot within g
                    const int sl = ch * 8 + g * 2 + d;
                    const int j0 = 2 * d;
                    uint32_t t1 = __byte_perm(X[j0],     Y[j0],     sel);
                    uint32_t t2 = __byte_perm(X[j0 + 1], Y[j0 + 1], sel);
                    uint32_t w01 = __byte_perm(t1, t2, 0x5410);
                    // 0/1 -> +1/-1 PER BYTE. w01+w01 is byte-safe (bytes<=1);
                    // __vsub4 subtracts per byte WITHOUT cross-byte borrow.
                    // (Plain 32-bit "0x01010101-2*w01" borrows into the next
                    // byte lane wherever a byte is 1 — the R16 correctness bug.)
                    S[sl * SW + q0] = __vsub4(0x01010101u, w01 + w01);

                    t1 = __byte_perm(X[j0],     Y[j0],     sel1);
                    t2 = __byte_perm(X[j0 + 1], Y[j0 + 1], sel1);
                    w01 = __byte_perm(t1, t2, 0x5410);
                    S[sl * SW + q0 + 1] = __vsub4(0x01010101u, w01 + w01);
                }
            }
        }
    }

    __syncthreads();

    // ---------------- Cross-wave L2 prefetch (loads-idle phase) ------------
    if (bx + WAVE < GRID) {
        const char* np = (const char*)((const uint4*)samples
                                       + (size_t)(bx + WAVE) * 8192);
        #pragma unroll
        for (int k2 = 0; k2 < 4; k2++)
            asm volatile("prefetch.global.L2 [%0];"
                         :: "l"(np + (size_t)(tid + 256 * k2) * 128));
    }

    // ---------------- Phase 2: C = S^T S via IMMA ---------------------------
    // Warps 0..3: row group R=w,   col groups {0,2,4,6,8} (8 = bias cols).
    // Warps 4..7: row group R=w-4, col groups {1,3,5,7}.
    const int R       = w & 3;
    const int cgStart = (w < 4) ? 0 : 1;
    const int nU      = (w < 4) ? 5 : 4;
    const int qrow0   = R * 16;
    const int g  = lane >> 2;        // group id
    const int t4 = lane & 3;         // thread in group

    int c_[5][4];
    #pragma unroll
    for (int u = 0; u < 5; u++)
        #pragma unroll
        for (int e = 0; e < 4; e++) c_[u][e] = 0;

    #pragma unroll 4
    for (int st = 0; st < 16; st++) {            // 16 k-steps of 32 samples
        const int sA = st * 8 + t4;
        const uint32_t a0 = S[sA * SW + qrow0 + g];
        const uint32_t a1 = S[sA * SW + qrow0 + 8 + g];
        const uint32_t a2 = S[(sA + 4) * SW + qrow0 + g];
        const uint32_t a3 = S[(sA + 4) * SW + qrow0 + 8 + g];
        #pragma unroll
        for (int u = 0; u < 5; u++) {
            if (u < nU) {
                const int col0 = (cgStart + 2 * u) * 8;
                const uint32_t b0 = S[sA * SW + col0 + g];
                const uint32_t b1 = S[(sA + 4) * SW + col0 + g];
                mma_s8(c_[u], a0, a1, a2, a3, b0, b1);
            }
        }
    }

    // ---------------- Epilogue: fold with K and bias ------------------------
    float acc = 0.f;
    #pragma unroll
    for (int u = 0; u < 5; u++) {
        if (u < nU) {
            const int col0 = (cgStart + 2 * u) * 8;
            const int r0 = qrow0 + g, r1 = r0 + 8;
            if (col0 < 64) {
                const int cA = col0 + 2 * t4, cB = cA + 1;
                acc += kern[r0 * NQ + cA] * (float)c_[u][0]
                     + kern[r0 * NQ + cB] * (float)c_[u][1]
                     + kern[r1 * NQ + cA] * (float)c_[u][2]
                     + kern[r1 * NQ + cB] * (float)c_[u][3];
            } else if (t4 == 0) {                 // bias column (q=64, ones)
                acc += bias[r0] * (float)c_[u][0]
                     + bias[r1] * (float)c_[u][2];
            }
        }
    }

    // ---------------- Reduction + fused gather ----------------------------
    #pragma unroll
    for (int o = 16; o > 0; o >>= 1)
        acc += __shfl_down_sync(0xffffffffu, acc, o);
    if (lane == 0) red[w] = acc;
    __syncthreads();

    if (tid == 0) {
        float s = 0.f;
        #pragma unroll
        for (int x = 0; x < NWARPS; x++) s += red[x];
        g_part[bx] = s;
        __threadfence();
        const unsigned int done = atomicAdd(&g_count, 1u);
        s_last = (done == GRID - 1);
    }
    __syncthreads();

    if (s_last) {
        __threadfence();
        for (int x = tid; x < NB; x += THREADS) {
            const int u = idx[x];
            const float* gp = &g_part[u * PARTS];
            float s = 0.f;
            #pragma unroll
            for (int q = 0; q < PARTS; q++) s += gp[q];
            out[x] = s * (1.0f / (float)NS);
        }
        if (tid == 0) g_count = 0u;   // reset for next graph replay
    }
}

extern "C" void kernel_launch(void* const* d_in, const int* in_sizes, int n_in,
                              void* d_out, int out_size)
{
    const int*   samples = (const int*)d_in[0];
    const int*   idx     = (const int*)d_in[1];
    const float* bias    = (const float*)d_in[2];
    const float* kern    = (const float*)d_in[3];
    float*       out     = (float*)d_out;

    energy_kernel<<<GRID, THREADS>>>(samples, idx, bias, kern, out);
}